// round 5
// baseline (speedup 1.0000x reference)
#include <cuda_runtime.h>
#include <cstdint>

// GramsEmbedding: out[b,s,:] = sum over UNIQUE v in {idx[0,b,s], idx[1,b,s]} of weight[v,:]
// K=2, B=2, S=1024, V=32000, D=128.
//
// ILP-4 version: each thread handles ONE column of FOUR CONTIGUOUS rows
// (group g covers rows 4g..4g+3). Level 1 collapses to two int4 (16B) loads
// -- the 4 gram0 indices and the 4 gram1 indices -- then level 2 issues 8
// independent weight gathers (MLP=8 per thread). 65536 threads, 256 CTAs x 256.
// idx int4 loads are warp-broadcast; gathers and stores are coalesced 128B.

#define ROWS      2048      // B * S
#define D         128
#define THREADS   256

__global__ __launch_bounds__(THREADS, 8)
void grams_embedding_kernel(const int4* __restrict__ idx4,   // [2][512] int4
                            const float* __restrict__ w,     // [32000][128]
                            float* __restrict__ out)         // [2048][128]
{
    int t   = blockIdx.x * THREADS + threadIdx.x;    // 0 .. 65535
    int g   = t >> 7;                                 // row group 0 .. 511
    int col = t & 127;                                // 0 .. 127

    // Level 1: two independent 16B idx loads (warp-broadcast)
    int4 ia = __ldg(&idx4[g]);               // gram0 indices for rows 4g..4g+3
    int4 ib = __ldg(&idx4[g + ROWS / 4]);    // gram1 indices for rows 4g..4g+3

    // Level 2: 8 independent gathers, 32-bit offsets
    float a0 = __ldg(&w[ia.x * D + col]);
    float a1 = __ldg(&w[ia.y * D + col]);
    float a2 = __ldg(&w[ia.z * D + col]);
    float a3 = __ldg(&w[ia.w * D + col]);
    float b0 = __ldg(&w[ib.x * D + col]);
    float b1 = __ldg(&w[ib.y * D + col]);
    float b2 = __ldg(&w[ib.z * D + col]);
    float b3 = __ldg(&w[ib.w * D + col]);

    int base = (g << 2) * D + col;           // row 4g, this col
    out[base        ] = a0 + (ib.x != ia.x ? b0 : 0.0f);
    out[base +     D] = a1 + (ib.y != ia.y ? b1 : 0.0f);
    out[base + 2 * D] = a2 + (ib.z != ia.z ? b2 : 0.0f);
    out[base + 3 * D] = a3 + (ib.w != ia.w ? b3 : 0.0f);
}

extern "C" void kernel_launch(void* const* d_in, const int* in_sizes, int n_in,
                              void* d_out, int out_size)
{
    const int4*  idx4 = (const int4*)d_in[0];
    const float* w    = (const float*)d_in[1];
    float*       out  = (float*)d_out;

    grams_embedding_kernel<<<(ROWS / 4 * D) / THREADS, THREADS>>>(idx4, w, out);
}

// round 6
// speedup vs baseline: 1.1939x; 1.1939x over previous
#include <cuda_runtime.h>
#include <cstdint>

// GramsEmbedding: out[b,s,:] = sum over UNIQUE v in {idx[0,b,s], idx[1,b,s]} of weight[v,:]
// K=2, B=2, S=1024, V=32000, D=128.
//
// Best-found operating point (R4): 131072 threads, 4 independent gathers per
// thread. Refinements:
//  - each thread owns one column of two CONTIGUOUS rows (2g, 2g+1) so the
//    4 idx loads compress to two int2 (8B) loads
//  - 256-thread CTAs -> 512 CTAs (4:3 per-SM balance instead of 2:1)
// idx loads warp-broadcast; gathers and stores coalesced 128B per warp.

#define ROWS      2048      // B * S
#define D         128
#define THREADS   256

__global__ __launch_bounds__(THREADS, 8)
void grams_embedding_kernel(const int2* __restrict__ idx2,   // [2][1024] int2
                            const float* __restrict__ w,     // [32000][128]
                            float* __restrict__ out)         // [2048][128]
{
    int t   = blockIdx.x * THREADS + threadIdx.x;    // 0 .. 131071
    int g   = t >> 7;                                 // row pair 0 .. 1023
    int col = t & 127;                                // 0 .. 127

    // Level 1: two independent 8B idx loads (warp-broadcast, 1 sector each)
    int2 ia = __ldg(&idx2[g]);               // gram0 indices, rows 2g / 2g+1
    int2 ib = __ldg(&idx2[g + ROWS / 2]);    // gram1 indices, rows 2g / 2g+1

    // Level 2: 4 independent gathers, 32-bit offsets
    float a0 = __ldg(&w[ia.x * D + col]);
    float a1 = __ldg(&w[ia.y * D + col]);
    float b0 = __ldg(&w[ib.x * D + col]);
    float b1 = __ldg(&w[ib.y * D + col]);

    int base = (g << 1) * D + col;           // row 2g, this col
    out[base    ] = a0 + (ib.x != ia.x ? b0 : 0.0f);
    out[base + D] = a1 + (ib.y != ia.y ? b1 : 0.0f);
}

extern "C" void kernel_launch(void* const* d_in, const int* in_sizes, int n_in,
                              void* d_out, int out_size)
{
    const int2*  idx2 = (const int2*)d_in[0];
    const float* w    = (const float*)d_in[1];
    float*       out  = (float*)d_out;

    grams_embedding_kernel<<<(ROWS / 2 * D) / THREADS, THREADS>>>(idx2, w, out);
}